// round 1
// baseline (speedup 1.0000x reference)
#include <cuda_runtime.h>
#include <cuda_bf16.h>

#define N 1024
#define D 128
#define H 128

// Scratch (allocation-free rule: __device__ globals)
__device__ __align__(16) float g_u[D];
__device__ __align__(16) float g_v[D];
__device__ float g_nb[N];         // node_part[j] + b_node + b_edge + wt_b
__device__ float g_consts;        // b_node + b_edge + wt_b

// ---------------------------------------------------------------------------
// Kernel 1: tiny setup. 1 block, 128 threads.
// u[d] = sum_h Wh[h,d]*w1[h] + Wt[h,d]*w2[h]
// v[d] = sum_h Wr[h,d]*w3[h]
// consts = bh@w1 + bt@w2 + br@w3 + wt_b[0]
// ---------------------------------------------------------------------------
__global__ void setup_kernel(const float* __restrict__ Wh,
                             const float* __restrict__ bh,
                             const float* __restrict__ Wt,
                             const float* __restrict__ bt,
                             const float* __restrict__ Wr,
                             const float* __restrict__ br,
                             const float* __restrict__ wt_w,
                             const float* __restrict__ wt_b) {
    int d = threadIdx.x;   // 0..127
    float u = 0.f, v = 0.f;
    #pragma unroll 4
    for (int h = 0; h < H; ++h) {
        float w1 = wt_w[h];
        float w2 = wt_w[H + h];
        float w3 = wt_w[2 * H + h];
        u += Wh[h * D + d] * w1 + Wt[h * D + d] * w2;
        v += Wr[h * D + d] * w3;
    }
    g_u[d] = u;
    g_v[d] = v;
    if (d == 0) {
        float c = wt_b[0];
        for (int h = 0; h < H; ++h) {
            c += bh[h] * wt_w[h] + bt[h] * wt_w[H + h] + br[h] * wt_w[2 * H + h];
        }
        g_consts = c;
    }
}

// ---------------------------------------------------------------------------
// Kernel 2: nb[j] = node_feat[j,:] @ u + consts.  One warp per j.
// Grid: 128 blocks x 256 threads (8 warps) -> 1024 warps.
// ---------------------------------------------------------------------------
__global__ void nodepart_kernel(const float* __restrict__ node_feat) {
    int warp = (blockIdx.x * blockDim.x + threadIdx.x) >> 5;
    int lane = threadIdx.x & 31;
    if (warp >= N) return;
    float4 u4 = reinterpret_cast<const float4*>(g_u)[lane];
    float4 x  = reinterpret_cast<const float4*>(node_feat + (size_t)warp * D)[lane];
    float dsum = x.x * u4.x + x.y * u4.y + x.z * u4.z + x.w * u4.w;
    #pragma unroll
    for (int o = 16; o > 0; o >>= 1) dsum += __shfl_xor_sync(0xffffffffu, dsum, o);
    if (lane == 0) g_nb[warp] = dsum + g_consts;
}

// ---------------------------------------------------------------------------
// Kernel 3: main streaming pass + fused softmax.
// One block per row i (1024 blocks, 1024 threads = 32 warps).
// Warp w computes e[j] for j in [w*32, w*32+32): lane loads one float4 of
// edge_feat[i,j,:] (32 lanes * 16B = the full 512B row, perfectly coalesced),
// dots with v, warp-reduces. Unroll 4 across j for MLP.
// Then block softmax over the 1024 shared values; coalesced store.
// ---------------------------------------------------------------------------
__global__ void __launch_bounds__(1024, 1)
main_kernel(const float* __restrict__ edge_feat, float* __restrict__ out) {
    const int i    = blockIdx.x;
    const int tid  = threadIdx.x;
    const int lane = tid & 31;
    const int w    = tid >> 5;

    __shared__ float se[N];
    __shared__ float sred[32];
    __shared__ float s_bcast;

    const float4 v4 = reinterpret_cast<const float4*>(g_v)[lane];
    const float4* base =
        reinterpret_cast<const float4*>(edge_feat + (size_t)i * N * D);

    const int j0 = w << 5;
    #pragma unroll
    for (int k = 0; k < 32; k += 4) {
        // 4 independent float4 loads in flight per lane
        float4 x0 = base[(size_t)(j0 + k + 0) * (D / 4) + lane];
        float4 x1 = base[(size_t)(j0 + k + 1) * (D / 4) + lane];
        float4 x2 = base[(size_t)(j0 + k + 2) * (D / 4) + lane];
        float4 x3 = base[(size_t)(j0 + k + 3) * (D / 4) + lane];
        float d0 = x0.x * v4.x + x0.y * v4.y + x0.z * v4.z + x0.w * v4.w;
        float d1 = x1.x * v4.x + x1.y * v4.y + x1.z * v4.z + x1.w * v4.w;
        float d2 = x2.x * v4.x + x2.y * v4.y + x2.z * v4.z + x2.w * v4.w;
        float d3 = x3.x * v4.x + x3.y * v4.y + x3.z * v4.z + x3.w * v4.w;
        #pragma unroll
        for (int o = 16; o > 0; o >>= 1) {
            d0 += __shfl_xor_sync(0xffffffffu, d0, o);
            d1 += __shfl_xor_sync(0xffffffffu, d1, o);
            d2 += __shfl_xor_sync(0xffffffffu, d2, o);
            d3 += __shfl_xor_sync(0xffffffffu, d3, o);
        }
        if (lane == 0) {
            se[j0 + k + 0] = d0 + g_nb[j0 + k + 0];
            se[j0 + k + 1] = d1 + g_nb[j0 + k + 1];
            se[j0 + k + 2] = d2 + g_nb[j0 + k + 2];
            se[j0 + k + 3] = d3 + g_nb[j0 + k + 3];
        }
    }
    __syncthreads();

    // ---- block softmax over se[0..1023], one element per thread ----
    float e = se[tid];

    // max reduce
    float m = e;
    #pragma unroll
    for (int o = 16; o > 0; o >>= 1)
        m = fmaxf(m, __shfl_xor_sync(0xffffffffu, m, o));
    if (lane == 0) sred[w] = m;
    __syncthreads();
    if (w == 0) {
        float mm = sred[lane];
        #pragma unroll
        for (int o = 16; o > 0; o >>= 1)
            mm = fmaxf(mm, __shfl_xor_sync(0xffffffffu, mm, o));
        if (lane == 0) s_bcast = mm;
    }
    __syncthreads();
    const float mmax = s_bcast;

    float p = __expf(e - mmax);

    // sum reduce
    float s = p;
    #pragma unroll
    for (int o = 16; o > 0; o >>= 1)
        s += __shfl_xor_sync(0xffffffffu, s, o);
    if (lane == 0) sred[w] = s;
    __syncthreads();
    if (w == 0) {
        float ss = sred[lane];
        #pragma unroll
        for (int o = 16; o > 0; o >>= 1)
            ss += __shfl_xor_sync(0xffffffffu, ss, o);
        if (lane == 0) s_bcast = ss;
    }
    __syncthreads();

    out[(size_t)i * N + tid] = p * (1.0f / s_bcast);
}

// ---------------------------------------------------------------------------
// Launcher. Input order per metadata:
// 0 node_feat (N,D) f32 | 1 edge_feat (N,N,D) f32 | 2 mask (unused)
// 3 Wh | 4 bh | 5 Wt | 6 bt | 7 Wr | 8 br | 9 wt_w | 10 wt_b
// ---------------------------------------------------------------------------
extern "C" void kernel_launch(void* const* d_in, const int* in_sizes, int n_in,
                              void* d_out, int out_size) {
    const float* node_feat = (const float*)d_in[0];
    const float* edge_feat = (const float*)d_in[1];
    const float* Wh   = (const float*)d_in[3];
    const float* bh   = (const float*)d_in[4];
    const float* Wt   = (const float*)d_in[5];
    const float* bt   = (const float*)d_in[6];
    const float* Wr   = (const float*)d_in[7];
    const float* br   = (const float*)d_in[8];
    const float* wt_w = (const float*)d_in[9];
    const float* wt_b = (const float*)d_in[10];
    float* out = (float*)d_out;

    setup_kernel<<<1, 128>>>(Wh, bh, Wt, bt, Wr, br, wt_w, wt_b);
    nodepart_kernel<<<128, 256>>>(node_feat);
    main_kernel<<<N, 1024>>>(edge_feat, out);
}

// round 2
// speedup vs baseline: 1.4626x; 1.4626x over previous
#include <cuda_runtime.h>
#include <cuda_bf16.h>

#define N 1024
#define D 128
#define H 128

// Scratch (allocation-free rule: __device__ globals)
__device__ __align__(16) float g_u[D];
__device__ __align__(16) float g_v[D];
__device__ float g_nb[N];         // node_part[j] + consts
__device__ float g_consts;        // bh@w1 + bt@w2 + br@w3 + wt_b[0]

// ---------------------------------------------------------------------------
// Kernel 1: setup. 1 block, 1024 threads.
// tid = g*128 + d (g in 0..7, d in 0..127). Group g sums h in [g*16, g*16+16).
// Partial sums reduced through shared memory. Fully unrolled inner loop for MLP.
// ---------------------------------------------------------------------------
__global__ void __launch_bounds__(1024, 1)
setup_kernel(const float* __restrict__ Wh,
             const float* __restrict__ bh,
             const float* __restrict__ Wt,
             const float* __restrict__ bt,
             const float* __restrict__ Wr,
             const float* __restrict__ br,
             const float* __restrict__ wt_w,
             const float* __restrict__ wt_b) {
    const int tid = threadIdx.x;
    const int d = tid & 127;     // column
    const int g = tid >> 7;      // h-group 0..7

    __shared__ float su[8][128];
    __shared__ float sv[8][128];
    __shared__ float sc[1024];

    float u = 0.f, v = 0.f;
    const int h0 = g * 16;
    #pragma unroll
    for (int k = 0; k < 16; ++k) {
        int h = h0 + k;
        float w1 = __ldg(&wt_w[h]);
        float w2 = __ldg(&wt_w[H + h]);
        float w3 = __ldg(&wt_w[2 * H + h]);
        u = fmaf(__ldg(&Wh[h * D + d]), w1, u);
        u = fmaf(__ldg(&Wt[h * D + d]), w2, u);
        v = fmaf(__ldg(&Wr[h * D + d]), w3, v);
    }
    su[g][d] = u;
    sv[g][d] = v;

    // consts partials: first 3*H=384 threads each handle one (bias, weight) pair
    float c = 0.f;
    if (tid < H)               c = bh[tid] * wt_w[tid];
    else if (tid < 2 * H)      c = bt[tid - H] * wt_w[tid];
    else if (tid < 3 * H)      c = br[tid - 2 * H] * wt_w[tid];
    sc[tid] = c;
    __syncthreads();

    if (tid < 128) {
        float uu = 0.f, vv = 0.f;
        #pragma unroll
        for (int gg = 0; gg < 8; ++gg) { uu += su[gg][tid]; vv += sv[gg][tid]; }
        g_u[tid] = uu;
        g_v[tid] = vv;
    }
    // reduce sc[0..383] -> consts (warp 31 does it serially-ish; tiny)
    if (tid == 0) {
        // tree-free: 384 adds by one thread would be slow; do strided partial first
    }
    __syncthreads();
    // parallel reduce sc over 384 entries: fold into 128 then warp-reduce
    if (tid < 128) {
        float cc = sc[tid] + sc[tid + 128] + sc[tid + 256];
        #pragma unroll
        for (int o = 16; o > 0; o >>= 1) cc += __shfl_xor_sync(0xffffffffu, cc, o);
        if ((tid & 31) == 0) sc[512 + (tid >> 5)] = cc;
    }
    __syncthreads();
    if (tid == 0) {
        g_consts = sc[512] + sc[513] + sc[514] + sc[515] + __ldg(&wt_b[0]);
    }
}

// ---------------------------------------------------------------------------
// Kernel 2: nb[j] = node_feat[j,:] @ u + consts.  One warp per j.
// Grid: 128 blocks x 256 threads (8 warps) -> 1024 warps.
// ---------------------------------------------------------------------------
__global__ void nodepart_kernel(const float* __restrict__ node_feat) {
    int warp = (blockIdx.x * blockDim.x + threadIdx.x) >> 5;
    int lane = threadIdx.x & 31;
    if (warp >= N) return;
    float4 u4 = reinterpret_cast<const float4*>(g_u)[lane];
    float4 x  = reinterpret_cast<const float4*>(node_feat + (size_t)warp * D)[lane];
    float dsum = x.x * u4.x + x.y * u4.y + x.z * u4.z + x.w * u4.w;
    #pragma unroll
    for (int o = 16; o > 0; o >>= 1) dsum += __shfl_xor_sync(0xffffffffu, dsum, o);
    if (lane == 0) g_nb[warp] = dsum + g_consts;
}

// ---------------------------------------------------------------------------
// Kernel 3: main streaming pass + fused softmax.
// One block per row i (1024 blocks, 1024 threads = 32 warps).
// Warp w computes e[j] for j in [w*32, w*32+32): lane loads one float4 of
// edge_feat[i,j,:] via __ldcs (streaming; no reuse), dots with v, warp-reduces.
// Unroll 4 across j for MLP. Then block softmax; coalesced store.
// ---------------------------------------------------------------------------
__global__ void __launch_bounds__(1024, 1)
main_kernel(const float* __restrict__ edge_feat, float* __restrict__ out) {
    const int i    = blockIdx.x;
    const int tid  = threadIdx.x;
    const int lane = tid & 31;
    const int w    = tid >> 5;

    __shared__ float se[N];
    __shared__ float sred[32];
    __shared__ float s_bcast;

    const float4 v4 = reinterpret_cast<const float4*>(g_v)[lane];
    const float4* base =
        reinterpret_cast<const float4*>(edge_feat + (size_t)i * N * D);

    const int j0 = w << 5;
    #pragma unroll
    for (int k = 0; k < 32; k += 4) {
        // 4 independent float4 streaming loads in flight per lane
        float4 x0 = __ldcs(&base[(size_t)(j0 + k + 0) * (D / 4) + lane]);
        float4 x1 = __ldcs(&base[(size_t)(j0 + k + 1) * (D / 4) + lane]);
        float4 x2 = __ldcs(&base[(size_t)(j0 + k + 2) * (D / 4) + lane]);
        float4 x3 = __ldcs(&base[(size_t)(j0 + k + 3) * (D / 4) + lane]);
        float d0 = x0.x * v4.x + x0.y * v4.y + x0.z * v4.z + x0.w * v4.w;
        float d1 = x1.x * v4.x + x1.y * v4.y + x1.z * v4.z + x1.w * v4.w;
        float d2 = x2.x * v4.x + x2.y * v4.y + x2.z * v4.z + x2.w * v4.w;
        float d3 = x3.x * v4.x + x3.y * v4.y + x3.z * v4.z + x3.w * v4.w;
        #pragma unroll
        for (int o = 16; o > 0; o >>= 1) {
            d0 += __shfl_xor_sync(0xffffffffu, d0, o);
            d1 += __shfl_xor_sync(0xffffffffu, d1, o);
            d2 += __shfl_xor_sync(0xffffffffu, d2, o);
            d3 += __shfl_xor_sync(0xffffffffu, d3, o);
        }
        if (lane == 0) {
            se[j0 + k + 0] = d0 + g_nb[j0 + k + 0];
            se[j0 + k + 1] = d1 + g_nb[j0 + k + 1];
            se[j0 + k + 2] = d2 + g_nb[j0 + k + 2];
            se[j0 + k + 3] = d3 + g_nb[j0 + k + 3];
        }
    }
    __syncthreads();

    // ---- block softmax over se[0..1023], one element per thread ----
    float e = se[tid];

    float m = e;
    #pragma unroll
    for (int o = 16; o > 0; o >>= 1)
        m = fmaxf(m, __shfl_xor_sync(0xffffffffu, m, o));
    if (lane == 0) sred[w] = m;
    __syncthreads();
    if (w == 0) {
        float mm = sred[lane];
        #pragma unroll
        for (int o = 16; o > 0; o >>= 1)
            mm = fmaxf(mm, __shfl_xor_sync(0xffffffffu, mm, o));
        if (lane == 0) s_bcast = mm;
    }
    __syncthreads();
    const float mmax = s_bcast;

    float p = __expf(e - mmax);

    float s = p;
    #pragma unroll
    for (int o = 16; o > 0; o >>= 1)
        s += __shfl_xor_sync(0xffffffffu, s, o);
    if (lane == 0) sred[w] = s;
    __syncthreads();
    if (w == 0) {
        float ss = sred[lane];
        #pragma unroll
        for (int o = 16; o > 0; o >>= 1)
            ss += __shfl_xor_sync(0xffffffffu, ss, o);
        if (lane == 0) s_bcast = ss;
    }
    __syncthreads();

    out[(size_t)i * N + tid] = p * (1.0f / s_bcast);
}

// ---------------------------------------------------------------------------
// Launcher. Input order per metadata:
// 0 node_feat (N,D) f32 | 1 edge_feat (N,N,D) f32 | 2 mask (unused)
// 3 Wh | 4 bh | 5 Wt | 6 bt | 7 Wr | 8 br | 9 wt_w | 10 wt_b
// ---------------------------------------------------------------------------
extern "C" void kernel_launch(void* const* d_in, const int* in_sizes, int n_in,
                              void* d_out, int out_size) {
    const float* node_feat = (const float*)d_in[0];
    const float* edge_feat = (const float*)d_in[1];
    const float* Wh   = (const float*)d_in[3];
    const float* bh   = (const float*)d_in[4];
    const float* Wt   = (const float*)d_in[5];
    const float* bt   = (const float*)d_in[6];
    const float* Wr   = (const float*)d_in[7];
    const float* br   = (const float*)d_in[8];
    const float* wt_w = (const float*)d_in[9];
    const float* wt_b = (const float*)d_in[10];
    float* out = (float*)d_out;

    setup_kernel<<<1, 1024>>>(Wh, bh, Wt, bt, Wr, br, wt_w, wt_b);
    nodepart_kernel<<<128, 256>>>(node_feat);
    main_kernel<<<N, 1024>>>(edge_feat, out);
}